// round 1
// baseline (speedup 1.0000x reference)
#include <cuda_runtime.h>

// Problem geometry
#define NX 512
#define NY 512
#define NZ 64
#define PLANE (NX * NY * NZ)      // 16777216 elements per component
#define UNITS (PLANE / 4)         // float4 units: 4194304
#define XSTRIDE (NY * NZ)         // 32768 floats between ix slices
#define YSTRIDE (NZ)              // 64 floats between iy rows

#define TPB 256
#define NBLOCKS 4096

// Scratch for deterministic two-stage reduction (no dynamic allocation allowed)
__device__ float g_partials[NBLOCKS];

// sum_j (a_j * b_j - c_j * d_j) over the 4 lanes
__device__ __forceinline__ float quad_cross(float4 a, float4 b, float4 c, float4 d) {
    float s;
    s  = fmaf(a.x, b.x, -c.x * d.x);
    s += fmaf(a.y, b.y, -c.y * d.y);
    s += fmaf(a.z, b.z, -c.z * d.z);
    s += fmaf(a.w, b.w, -c.w * d.w);
    return s;
}

__global__ void __launch_bounds__(TPB)
dmi_partial_kernel(const float* __restrict__ x) {
    const float* __restrict__ Xc = x;             // component 0 (mx)
    const float* __restrict__ Yc = x + PLANE;     // component 1 (my)
    const float* __restrict__ Zc = x + 2 * PLANE; // component 2 (mz)

    float acc = 0.0f;

    for (int u = blockIdx.x * TPB + threadIdx.x; u < UNITS; u += NBLOCKS * TPB) {
        const int e   = u << 2;         // element index (z-contiguous), multiple of 4
        const int row = e >> 6;         // e / NZ  -> combined (ix, iy)
        const int iy  = row & (NY - 1);
        const int ix  = row >> 9;       // row / NY

        const float4 px = *reinterpret_cast<const float4*>(Xc + e);
        const float4 py = *reinterpret_cast<const float4*>(Yc + e);
        const float4 pz = *reinterpret_cast<const float4*>(Zc + e);

        // (m_p x m_{p-x})_y = pz*nx.x - px*nx.z   (zero when ix == 0)
        if (ix > 0) {
            const float4 nxx = *reinterpret_cast<const float4*>(Xc + e - XSTRIDE);
            const float4 nxz = *reinterpret_cast<const float4*>(Zc + e - XSTRIDE);
            acc += quad_cross(pz, nxx, px, nxz);
        }
        // -(m_p x m_{p-y})_x = pz*ny.y - py*ny.z  (zero when iy == 0)
        if (iy > 0) {
            const float4 nyy = *reinterpret_cast<const float4*>(Yc + e - YSTRIDE);
            const float4 nyz = *reinterpret_cast<const float4*>(Zc + e - YSTRIDE);
            acc += quad_cross(pz, nyy, py, nyz);
        }
    }

    // warp reduction
    #pragma unroll
    for (int off = 16; off > 0; off >>= 1)
        acc += __shfl_down_sync(0xFFFFFFFFu, acc, off);

    __shared__ float warp_sums[TPB / 32];
    const int lane = threadIdx.x & 31;
    const int wid  = threadIdx.x >> 5;
    if (lane == 0) warp_sums[wid] = acc;
    __syncthreads();

    if (wid == 0) {
        float v = (lane < TPB / 32) ? warp_sums[lane] : 0.0f;
        #pragma unroll
        for (int off = 4; off > 0; off >>= 1)
            v += __shfl_down_sync(0xFFFFFFFFu, v, off);
        if (lane == 0) g_partials[blockIdx.x] = v;
    }
}

__global__ void __launch_bounds__(1024)
dmi_final_kernel(const float* __restrict__ D, float* __restrict__ out) {
    double acc = 0.0;
    for (int i = threadIdx.x; i < NBLOCKS; i += 1024)
        acc += (double)g_partials[i];

    #pragma unroll
    for (int off = 16; off > 0; off >>= 1)
        acc += __shfl_down_sync(0xFFFFFFFFu, acc, off);

    __shared__ double warp_sums[32];
    const int lane = threadIdx.x & 31;
    const int wid  = threadIdx.x >> 5;
    if (lane == 0) warp_sums[wid] = acc;
    __syncthreads();

    if (wid == 0) {
        double v = (lane < 32) ? warp_sums[lane] : 0.0;
        #pragma unroll
        for (int off = 16; off > 0; off >>= 1)
            v += __shfl_down_sync(0xFFFFFFFFu, v, off);
        if (lane == 0) {
            // result = 0.5 * D * cellsize^2 * mean(d1+d2+d3+d4)
            //        = D * cellsize^2 * (sum of backward-neighbor terms) / N
            const double cellsize2 = 4e-18;  // (2e-9)^2
            out[0] = (float)(v * (double)D[0] * cellsize2 / (double)PLANE);
        }
    }
}

extern "C" void kernel_launch(void* const* d_in, const int* in_sizes, int n_in,
                              void* d_out, int out_size) {
    const float* x = (const float*)d_in[0];
    // d_in[1] = geo : unused by the forward pass
    const float* D = (const float*)d_in[2];
    float* out = (float*)d_out;

    dmi_partial_kernel<<<NBLOCKS, TPB>>>(x);
    dmi_final_kernel<<<1, 1024>>>(D, out);
}